// round 12
// baseline (speedup 1.0000x reference)
#include <cuda_runtime.h>
#include <cuda_bf16.h>
#include <cstdint>

// Problem constants (fixed: B=8, S=4096, D=512, CD=4096)
#define N_ROWS 32768
#define DIM    512
#define KCODES 4096

// cand kernel: persistent CTAs, work item = (256-row tile) x (512-code chunk)
#define M_CTA    256
#define N_CHUNK  512
#define N_TILE   128                 // codes per B stage
#define BKB      128                 // int8 K elems per 128B row chunk
#define CHUNKS   (DIM / BKB)         // 4
#define NT_ITEM  (N_CHUNK / N_TILE)  // 4
#define IT_ITEM  (NT_ITEM * CHUNKS)  // 16 iters per item
#define N_ITEMS  ((N_ROWS / M_CTA) * (KCODES / N_CHUNK))  // 1024
#define GRID     148                 // persistent, one per SM
#define NTHR     512

#define QS 23.0f                     // int8 quant scale
#define DELTA 5000.0f                // rescore margin (scaled units, ~17 sigma)

// smem: [align 1KB][A 128KB][B 3x16KB]
#define A_BYTES   (M_CTA * DIM)              // 131072
#define BSTAGE    (N_TILE * BKB)             // 16384
#define DYN_SMEM  (1024 + A_BYTES + 3 * BSTAGE)  // 181248

// Scratch (device globals; no allocation allowed)
__device__ __align__(16) float  g_c2[KCODES];    // exact 0.5*||c||^2
__device__ __align__(16) float  g_c2s[KCODES];   // 0.5*||c||^2 * QS^2
__device__ int    g_cand[N_ROWS * 64];           // top-4 per 256-code window
__device__ float  g_csc[N_ROWS * 64];            // their scaled scores
__device__ int    g_work;                        // persistent work counter
__device__ double g_loss;
__device__ __align__(16) uint8_t g_cb8[KCODES * DIM];  // 2MB s8

// ---------------------------------------------------------------------------
// PTX helpers (sm_80-level only: cp.async, ldmatrix, mma.sync s8)
// ---------------------------------------------------------------------------
__device__ __forceinline__ uint32_t smem_u32(const void* p) {
    uint32_t a;
    asm("{ .reg .u64 t; cvta.to.shared.u64 t, %1; cvt.u32.u64 %0, t; }"
        : "=r"(a) : "l"(p));
    return a;
}

#define SW128(off) ((off) ^ (((off) >> 3) & 0x70))

#define CP16(dst, src) \
    asm volatile("cp.async.cg.shared.global [%0], [%1], 16;" \
                 :: "r"(dst), "l"(src) : "memory")

#define LDSM4(r0, r1, r2, r3, addr) \
    asm volatile("ldmatrix.sync.aligned.m8n8.x4.shared.b16 {%0,%1,%2,%3}, [%4];" \
                 : "=r"(r0), "=r"(r1), "=r"(r2), "=r"(r3) : "r"(addr))

#define MMA_S8(d, a, b) \
    asm volatile("mma.sync.aligned.m16n8k32.row.col.s32.s8.s8.s32 " \
                 "{%0,%1,%2,%3}, {%4,%5,%6,%7}, {%8,%9}, {%0,%1,%2,%3};" \
                 : "+r"((d)[0]), "+r"((d)[1]), "+r"((d)[2]), "+r"((d)[3]) \
                 : "r"((a)[0]), "r"((a)[1]), "r"((a)[2]), "r"((a)[3]), \
                   "r"((b)[0]), "r"((b)[1]))

__device__ __forceinline__ uint32_t to_s8x4(float4 v) {
    int a = __float2int_rn(fminf(fmaxf(v.x * QS, -127.f), 127.f));
    int b = __float2int_rn(fminf(fmaxf(v.y * QS, -127.f), 127.f));
    int c = __float2int_rn(fminf(fmaxf(v.z * QS, -127.f), 127.f));
    int d = __float2int_rn(fminf(fmaxf(v.w * QS, -127.f), 127.f));
    return (uint32_t)(a & 0xff) | ((uint32_t)(b & 0xff) << 8) |
           ((uint32_t)(c & 0xff) << 16) | ((uint32_t)(d & 0xff) << 24);
}

// sorted ascending top-4 insert
__device__ __forceinline__ void t4_insert(float (&v)[4], int (&ix)[4],
                                          float s, int i) {
    if (s < v[3]) {
        if (s < v[1]) {
            if (s < v[0]) {
                v[3]=v[2]; ix[3]=ix[2]; v[2]=v[1]; ix[2]=ix[1];
                v[1]=v[0]; ix[1]=ix[0]; v[0]=s; ix[0]=i;
            } else {
                v[3]=v[2]; ix[3]=ix[2]; v[2]=v[1]; ix[2]=ix[1];
                v[1]=s; ix[1]=i;
            }
        } else {
            if (s < v[2]) { v[3]=v[2]; ix[3]=ix[2]; v[2]=s; ix[2]=i; }
            else          { v[3]=s; ix[3]=i; }
        }
    }
}

// ---------------------------------------------------------------------------
// Prep: codebook s8 quantization + c2 tables + reset work counter/loss
// ---------------------------------------------------------------------------
__global__ void prep_cb(const float* __restrict__ cb) {
    int n = blockIdx.x, t = threadIdx.x;  // 4096 x 128
    float4 v = ((const float4*)(cb + (size_t)n * DIM))[t];
    ((uint32_t*)g_cb8)[(size_t)n * 128 + t] = to_s8x4(v);

    float s = v.x * v.x + v.y * v.y + v.z * v.z + v.w * v.w;
    #pragma unroll
    for (int off = 16; off > 0; off >>= 1)
        s += __shfl_down_sync(0xffffffffu, s, off);
    __shared__ float ws[4];
    if ((t & 31) == 0) ws[t >> 5] = s;
    __syncthreads();
    if (t == 0) {
        float c2 = 0.5f * (ws[0] + ws[1] + ws[2] + ws[3]);
        g_c2[n]  = c2;
        g_c2s[n] = c2 * (QS * QS);
        if (n == 0) { g_loss = 0.0; g_work = 0; }
    }
}

// ---------------------------------------------------------------------------
// Kernel 1: persistent int8 IMMA distance GEMM + per-window top-4.
// 148 CTAs x 512 threads pull items (row_tile, code_chunk) from g_work.
// Item = 256 rows x 512 codes x K512. Output: top-4 per (row, 256-code
// window) -> 64 candidates/row (stronger contract than the verified R10).
// ---------------------------------------------------------------------------
__global__ __launch_bounds__(NTHR, 1)
void cand_kernel(const float* __restrict__ x) {
    extern __shared__ char dsm[];
    __shared__ int s_item;
    const uint32_t sraw = smem_u32(dsm);
    const uint32_t sb   = (sraw + 1023u) & ~1023u;
    const uint32_t Ab = sb;
    const uint32_t Bb = sb + A_BYTES;

    const int tid  = threadIdx.x;
    const int lane = tid & 31, wid = tid >> 5;   // 16 warps
    const int warpM = wid & 7, warpN = wid >> 3; // 8 (M) x 2 (N)

    // ldmatrix per-thread address constants
    const uint32_t arow = (uint32_t)((lane & 7) + ((lane & 8) ? 8 : 0));
    const uint32_t asel = (lane & 16) ? 16u : 0u;
    const uint32_t axr  = (arow & 7u) << 4;
    const uint32_t abase0 = (uint32_t)(warpM * 32 + (int)arow) * 128u;
    const uint32_t abase1 = abase0 + 16u * 128u;
    const uint32_t brow = (uint32_t)((lane & 7) + ((lane & 16) ? 8 : 0));
    const uint32_t bsel = (lane & 8) ? 16u : 0u;
    const uint32_t bxr  = (brow & 7u) << 4;
    const uint32_t bstart = (uint32_t)(warpN * 64 + (int)brow) * 128u;

    int cur_rt = -1;

    for (;;) {
        if (tid == 0) s_item = atomicAdd(&g_work, 1);
        __syncthreads();                 // also: prior item's A reads done
        const int item = s_item;
        __syncthreads();                 // s_item consumed before next write
        if (item >= N_ITEMS) break;
        const int rt = item >> 3;        // row tile (consecutive items share)
        const int ch = item & 7;         // code chunk
        const int m0 = rt * M_CTA;
        const int c0 = ch * N_CHUNK;

        // ---- A (re)load: 256 rows x 512 fp32 -> s8 swizzled smem ----------
        if (rt != cur_rt) {
            const float4* xv4 = (const float4*)(x + (size_t)m0 * DIM);
            #pragma unroll
            for (int i = 0; i < 64; i++) {
                int f   = tid + i * 512;
                int row = f >> 7, q = f & 127;
                int chk = q >> 5, cs = q & 31;
                uint32_t pk = to_s8x4(xv4[f]);
                uint32_t off = (uint32_t)row * 128u + (uint32_t)cs * 4u;
                uint32_t dst = Ab + (uint32_t)chk * 32768u + SW128(off);
                asm volatile("st.shared.u32 [%0], %1;" :: "r"(dst), "r"(pk) : "memory");
            }
            cur_rt = rt;
            __syncthreads();
        }

        // ---- B prologue: stages for it=0,1 --------------------------------
        #pragma unroll
        for (int pre = 0; pre < 2; pre++) {
            #pragma unroll
            for (int j = 0; j < 2; j++) {
                int e = tid + j * 512;
                int row = e >> 3, seg = e & 7;
                const uint8_t* src =
                    g_cb8 + (size_t)(c0 + row) * DIM + pre * BKB + seg * 16;
                uint32_t dst = Bb + (uint32_t)pre * BSTAGE + (uint32_t)row * 128u +
                               (((uint32_t)seg * 16u) ^ (((uint32_t)row & 7u) << 4));
                CP16(dst, src);
            }
            asm volatile("cp.async.commit_group;" ::: "memory");
        }

        int acc[2][8][4];
        #pragma unroll
        for (int mt = 0; mt < 2; mt++)
            #pragma unroll
            for (int p = 0; p < 8; p++)
                #pragma unroll
                for (int c = 0; c < 4; c++) acc[mt][p][c] = 0;

        float t4v[4][4];
        int   t4i[4][4];
        #pragma unroll
        for (int r = 0; r < 4; r++)
            #pragma unroll
            for (int j = 0; j < 4; j++) { t4v[r][j] = 3.4e38f; t4i[r][j] = 0; }

        // ---- item main loop: 16 iters ------------------------------------
        for (int it = 0; it < IT_ITEM; it++) {
            const int nt = it >> 2, kc = it & 3, s = it % 3;
            asm volatile("cp.async.wait_group 1;" ::: "memory");
            __syncthreads();

            const int it2 = it + 2;
            if (it2 < IT_ITEM) {
                const int nt2 = it2 >> 2, kc2 = it2 & 3, s2 = it2 % 3;
                #pragma unroll
                for (int j = 0; j < 2; j++) {
                    int e = tid + j * 512;
                    int row = e >> 3, seg = e & 7;
                    const uint8_t* src = g_cb8 +
                        (size_t)(c0 + nt2 * N_TILE + row) * DIM + kc2 * BKB + seg * 16;
                    uint32_t dst = Bb + (uint32_t)s2 * BSTAGE + (uint32_t)row * 128u +
                                   (((uint32_t)seg * 16u) ^ (((uint32_t)row & 7u) << 4));
                    CP16(dst, src);
                }
            }
            asm volatile("cp.async.commit_group;" ::: "memory");

            const uint32_t Achunk = Ab + (uint32_t)kc * 32768u;
            const uint32_t Bs     = Bb + (uint32_t)s * BSTAGE;
            #pragma unroll
            for (int ks = 0; ks < 4; ks++) {
                const uint32_t koA = (((uint32_t)(ks * 32)) + asel) ^ axr;
                uint32_t a0[4], a1[4];
                LDSM4(a0[0], a0[1], a0[2], a0[3], Achunk + abase0 + koA);
                LDSM4(a1[0], a1[1], a1[2], a1[3], Achunk + abase1 + koA);
                const uint32_t koB = (((uint32_t)(ks * 32)) + bsel) ^ bxr;
                uint32_t bb[8][2];
                #pragma unroll
                for (int p = 0; p < 4; p++) {
                    uint32_t r0, r1, r2, r3;
                    LDSM4(r0, r1, r2, r3, Bs + bstart + (uint32_t)p * 2048u + koB);
                    bb[2 * p][0] = r0; bb[2 * p][1] = r1;
                    bb[2 * p + 1][0] = r2; bb[2 * p + 1][1] = r3;
                }
                #pragma unroll
                for (int p = 0; p < 8; p++) {
                    MMA_S8(acc[0][p], a0, bb[p]);
                    MMA_S8(acc[1][p], a1, bb[p]);
                }
            }

            if (kc == 3) {
                #pragma unroll
                for (int mt = 0; mt < 2; mt++) {
                    #pragma unroll
                    for (int p = 0; p < 8; p++) {
                        const int ng = c0 + nt * N_TILE + warpN * 64 + p * 8 + 2 * (lane & 3);
                        const float2 c2 = __ldg((const float2*)(g_c2s + ng));
                        t4_insert(t4v[mt * 2 + 0], t4i[mt * 2 + 0], c2.x - (float)acc[mt][p][0], ng);
                        t4_insert(t4v[mt * 2 + 0], t4i[mt * 2 + 0], c2.y - (float)acc[mt][p][1], ng + 1);
                        t4_insert(t4v[mt * 2 + 1], t4i[mt * 2 + 1], c2.x - (float)acc[mt][p][2], ng);
                        t4_insert(t4v[mt * 2 + 1], t4i[mt * 2 + 1], c2.y - (float)acc[mt][p][3], ng + 1);
                        acc[mt][p][0] = 0; acc[mt][p][1] = 0;
                        acc[mt][p][2] = 0; acc[mt][p][3] = 0;
                    }
                }
            }
        }

        // ---- merge within quad (same row), write per-window top-4 --------
        #pragma unroll
        for (int rs = 0; rs < 4; rs++) {
            #pragma unroll
            for (int delta = 1; delta <= 2; delta <<= 1) {
                float ov[4]; int oi[4];
                #pragma unroll
                for (int j = 0; j < 4; j++) {
                    ov[j] = __shfl_xor_sync(0xffffffffu, t4v[rs][j], delta);
                    oi[j] = __shfl_xor_sync(0xffffffffu, t4i[rs][j], delta);
                }
                #pragma unroll
                for (int j = 0; j < 4; j++) t4_insert(t4v[rs], t4i[rs], ov[j], oi[j]);
            }
        }
        if ((lane & 3) == 0) {
            #pragma unroll
            for (int rs = 0; rs < 4; rs++) {
                int row_local = warpM * 32 + (rs >> 1) * 16 + ((rs & 1) << 3) + (lane >> 2);
                size_t base = (size_t)(m0 + row_local) * 64 + ch * 8 + warpN * 4;
                #pragma unroll
                for (int j = 0; j < 4; j++) {
                    g_cand[base + j] = t4i[rs][j];
                    g_csc[base + j]  = t4v[rs][j];
                }
            }
        }
        // no sync needed here: next loop iteration begins with __syncthreads
    }
}

// ---------------------------------------------------------------------------
// Kernel 2: warp-per-row margin-pruned exact fp32 rescore + gather + loss.
// 64 candidate slots/row; prune by scaled-score margin (expected ~1.3 gathered).
// No __syncthreads in the hot path. out_near base 8B aligned -> float2 stores.
// ---------------------------------------------------------------------------
__global__ __launch_bounds__(256)
void rescore_gather_kernel(const float* __restrict__ x,
                           const float* __restrict__ cb,
                           float* __restrict__ out_enc,
                           float* __restrict__ out_near) {
    const int lane = threadIdx.x & 31;
    const int row  = blockIdx.x * 8 + (threadIdx.x >> 5);  // 4096 blocks x 8 warps

    // x row in registers: 4 x float4 per lane, coalesced
    const float4* xr = (const float4*)(x + (size_t)row * DIM);
    float4 xv[4];
    #pragma unroll
    for (int k = 0; k < 4; k++) xv[k] = xr[lane + 32 * k];

    // candidate meta: 2 slots per lane
    const int   i0 = g_cand[(size_t)row * 64 + lane];
    const int   i1 = g_cand[(size_t)row * 64 + 32 + lane];
    const float s0 = g_csc[(size_t)row * 64 + lane];
    const float s1 = g_csc[(size_t)row * 64 + 32 + lane];
    float m = fminf(s0, s1);
    #pragma unroll
    for (int off = 16; off > 0; off >>= 1)
        m = fminf(m, __shfl_xor_sync(0xffffffffu, m, off));
    const float cut = m + DELTA;

    unsigned bits0 = __ballot_sync(0xffffffffu, s0 <= cut);
    unsigned bits1 = __ballot_sync(0xffffffffu, s1 <= cut);

    float  best = 3.4e38f;
    int    bi   = 0x7fffffff;
    float4 cbest[4];
    #pragma unroll
    for (int k = 0; k < 4; k++) cbest[k] = make_float4(0.f, 0.f, 0.f, 0.f);

    #pragma unroll
    for (int half = 0; half < 2; half++) {
        unsigned bits = half ? bits1 : bits0;
        while (bits) {
            const int b = __ffs(bits) - 1;
            bits &= bits - 1;
            const int ci = __shfl_sync(0xffffffffu, half ? i1 : i0, b);
            const float4* cr = (const float4*)(cb + (size_t)ci * DIM);
            float4 cv[4];
            float p = 0.f;
            #pragma unroll
            for (int k = 0; k < 4; k++) {
                cv[k] = cr[lane + 32 * k];
                p += xv[k].x * cv[k].x + xv[k].y * cv[k].y +
                     xv[k].z * cv[k].z + xv[k].w * cv[k].w;
            }
            #pragma unroll
            for (int off = 16; off > 0; off >>= 1)
                p += __shfl_xor_sync(0xffffffffu, p, off);
            const float s = g_c2[ci] - p;  // identical on all lanes
            if (s < best || (s == best && ci < bi)) {
                best = s; bi = ci;
                #pragma unroll
                for (int k = 0; k < 4; k++) cbest[k] = cv[k];
            }
        }
    }

    if (lane == 0) out_enc[row] = (float)bi;

    float2* orow = (float2*)(out_near + (size_t)row * DIM);
    float ss = 0.f;
    #pragma unroll
    for (int k = 0; k < 4; k++) {
        const int fi = lane + 32 * k;  // float4 index in row
        orow[2 * fi]     = make_float2(cbest[k].x, cbest[k].y);
        orow[2 * fi + 1] = make_float2(cbest[k].z, cbest[k].w);
        const float dx = xv[k].x - cbest[k].x, dy = xv[k].y - cbest[k].y;
        const float dz = xv[k].z - cbest[k].z, dw = xv[k].w - cbest[k].w;
        ss += dx * dx + dy * dy + dz * dz + dw * dw;
    }
    #pragma unroll
    for (int off = 16; off > 0; off >>= 1)
        ss += __shfl_down_sync(0xffffffffu, ss, off);
    if (lane == 0) atomicAdd(&g_loss, (double)ss);
}

__global__ void finalize_kernel(float* __restrict__ out_losses) {
    double mean = g_loss / ((double)N_ROWS * (double)DIM);
    out_losses[0] = (float)mean;
    out_losses[1] = (float)mean;
}

// ---------------------------------------------------------------------------
// Output layout (float32): [0,32768) encoding; [32768,32770) losses;
// [32770, ...) nearest (base only 8B aligned).
// ---------------------------------------------------------------------------
extern "C" void kernel_launch(void* const* d_in, const int* in_sizes, int n_in,
                              void* d_out, int out_size) {
    const float* x  = (const float*)d_in[0];
    const float* cb = (const float*)d_in[1];
    if (n_in >= 2 && in_sizes[0] == KCODES * DIM && in_sizes[1] == N_ROWS * DIM) {
        const float* tmp = x; x = cb; cb = tmp;
    }

    float* out        = (float*)d_out;
    float* out_enc    = out;
    float* out_losses = out + N_ROWS;
    float* out_near   = out + N_ROWS + 2;

    static int smem_set = 0;
    if (!smem_set) {
        cudaFuncSetAttribute(cand_kernel,
                             cudaFuncAttributeMaxDynamicSharedMemorySize, DYN_SMEM);
        smem_set = 1;
    }

    prep_cb<<<KCODES, 128>>>(cb);
    cand_kernel<<<GRID, NTHR, DYN_SMEM>>>(x);
    rescore_gather_kernel<<<N_ROWS / 8, 256>>>(x, cb, out_enc, out_near);
    finalize_kernel<<<1, 1>>>(out_losses);
}